// round 1
// baseline (speedup 1.0000x reference)
#include <cuda_runtime.h>
#include <cstdint>
#include <cstddef>

#define NNODES 16384
#define FDIM   768
#define H1     4
#define DEG    4

// ---------------- scratch (device globals; no allocation allowed) ----------
__device__ float g_P1[FDIM * 8];                       // [k][j] j: 0..3 src heads, 4..7 dst heads
__device__ float g_P2[FDIM * 2];                       // [k][j] j: 0 src, 1 dst
__device__ float g_W1p[(size_t)4 * FDIM * FDIM];       // [3072, 768] repacked W1 * 0.25
__device__ float g_e1[(size_t)NNODES * 8];
__device__ float g_e2[(size_t)NNODES * 2];
__device__ float g_agg1[(size_t)NNODES * 4 * FDIM];    // [N, 3072]
__device__ float g_agg2[(size_t)NNODES * FDIM];        // [N, 768]
__device__ float g_pre[(size_t)NNODES * FDIM];         // GEMM output (reused both layers)
__device__ float g_x1[(size_t)NNODES * FDIM];
__device__ int   g_is64;

// ---------------- helpers ---------------------------------------------------
__device__ __forceinline__ float block_reduce_256(float v, float* red) {
#pragma unroll
    for (int o = 16; o; o >>= 1) v += __shfl_down_sync(0xffffffffu, v, o);
    if ((threadIdx.x & 31) == 0) red[threadIdx.x >> 5] = v;
    __syncthreads();
    float r = 0.f;
    if (threadIdx.x < 8) r = red[threadIdx.x];
    if (threadIdx.x < 32) {
#pragma unroll
        for (int o = 4; o; o >>= 1) r += __shfl_down_sync(0xffu, r, o);
    }
    return r;  // valid in thread 0
}

// ---------------- edge dtype probe ------------------------------------------
// JAX with x64 disabled gives int32 edge_index; if x64 were enabled it would be
// int64. Probe: read first 1024 u64 words of the src row. With int32 payload,
// odd int32 slots are random node ids (>0 w.h.p.) -> some u64 > 2^32.
__global__ void detect_kernel(const unsigned long long* __restrict__ p) {
    __shared__ int bad;
    if (threadIdx.x == 0) bad = 0;
    __syncthreads();
    for (int i = threadIdx.x; i < 1024; i += blockDim.x)
        if (p[i] > 0xFFFFFFFFull) bad = 1;
    __syncthreads();
    if (threadIdx.x == 0) g_is64 = bad ? 0 : 1;
}

// ---------------- attention projection vectors P = W_h @ a_h ----------------
__global__ void __launch_bounds__(256) build_p(
    const float* __restrict__ W1, const float* __restrict__ a1s, const float* __restrict__ a1d,
    const float* __restrict__ W2, const float* __restrict__ a2s, const float* __restrict__ a2d)
{
    __shared__ float red[8];
    int k = blockIdx.x, j = blockIdx.y;
    const float *w, *a;
    if (j < 8) {
        int h = j & 3;
        w = W1 + (size_t)k * (4 * FDIM) + h * FDIM;
        a = (j < 4 ? a1s : a1d) + h * FDIM;
    } else {
        w = W2 + (size_t)k * FDIM;
        a = (j == 8) ? a2s : a2d;
    }
    float s = 0.f;
    for (int d = threadIdx.x; d < FDIM; d += 256) s += w[d] * a[d];
    float tot = block_reduce_256(s, red);
    if (threadIdx.x == 0) {
        if (j < 8) g_P1[k * 8 + j] = tot;
        else       g_P2[k * 2 + (j - 8)] = tot;
    }
}

// ---------------- repack W1 for head-mean-folded GEMM -----------------------
// W1p[h*768 + k, j] = 0.25 * W1[k, h*768 + j]
__global__ void __launch_bounds__(256) build_w1p(const float* __restrict__ W1) {
    size_t idx = (size_t)blockIdx.x * 256 + threadIdx.x;
    if (idx >= (size_t)4 * FDIM * FDIM) return;
    int j = (int)(idx % FDIM);
    int r = (int)(idx / FDIM);     // h*768 + k
    int h = r / FDIM, k = r % FDIM;
    g_W1p[idx] = 0.25f * W1[(size_t)k * (4 * FDIM) + h * FDIM + j];
}

// ---------------- per-node logits e = x @ P ----------------------------------
template <int NJ>
__global__ void __launch_bounds__(256) compute_e(
    const float* __restrict__ x, const float* __restrict__ P, float* __restrict__ e)
{
    __shared__ float sP[FDIM * NJ];
    for (int i = threadIdx.x; i < FDIM * NJ; i += 256) sP[i] = P[i];
    __syncthreads();
    int warp = threadIdx.x >> 5, lane = threadIdx.x & 31;
    for (int n = blockIdx.x * 8 + warp; n < NNODES; n += gridDim.x * 8) {
        const float* xr = x + (size_t)n * FDIM;
        float acc[NJ];
#pragma unroll
        for (int j = 0; j < NJ; j++) acc[j] = 0.f;
        for (int k = lane; k < FDIM; k += 32) {
            float xv = xr[k];
#pragma unroll
            for (int j = 0; j < NJ; j++) acc[j] += xv * sP[k * NJ + j];
        }
#pragma unroll
        for (int j = 0; j < NJ; j++) {
            float v = acc[j];
#pragma unroll
            for (int o = 16; o; o >>= 1) v += __shfl_down_sync(0xffffffffu, v, o);
            if (lane == 0) e[(size_t)n * NJ + j] = v;
        }
    }
}

// ---------------- softmax + weighted gather in x-space ----------------------
template <int H, int NJ>
__global__ void __launch_bounds__(256) aggregate(
    const float* __restrict__ x, const float* __restrict__ e,
    const void* __restrict__ edge, float* __restrict__ agg)
{
    int n = blockIdx.x;
    __shared__ int   s_src[5];
    __shared__ float s_alpha[H][5];
    int tid = threadIdx.x;
    if (tid < 5) {
        int sv = n;  // self loop
        if (tid < 4) {
            sv = g_is64 ? (int)((const long long*)edge)[(size_t)DEG * n + tid]
                        : ((const int*)edge)[DEG * n + tid];
        }
        s_src[tid] = sv;
    }
    __syncthreads();
    if (tid < H) {
        float ed = e[(size_t)n * NJ + H + tid];
        float l[5];
#pragma unroll
        for (int k = 0; k < 5; k++) {
            float v = e[(size_t)s_src[k] * NJ + tid] + ed;
            l[k] = v >= 0.f ? v : 0.2f * v;          // leaky_relu(0.2)
        }
        float m = l[0];
#pragma unroll
        for (int k = 1; k < 5; k++) m = fmaxf(m, l[k]);
        float s = 0.f;
#pragma unroll
        for (int k = 0; k < 5; k++) { l[k] = expf(l[k] - m); s += l[k]; }
        float inv = 1.f / (s + 1e-16f);
#pragma unroll
        for (int k = 0; k < 5; k++) s_alpha[tid][k] = l[k] * inv;
    }
    __syncthreads();
    for (int d = tid; d < FDIM; d += 256) {
        float xv[5];
#pragma unroll
        for (int k = 0; k < 5; k++) xv[k] = x[(size_t)s_src[k] * FDIM + d];
#pragma unroll
        for (int h = 0; h < H; h++) {
            float a0 = 0.f;
#pragma unroll
            for (int k = 0; k < 5; k++) a0 += s_alpha[h][k] * xv[k];
            agg[((size_t)n * H + h) * FDIM + d] = a0;
        }
    }
}

// ---------------- fp32 SGEMM, C = A@B + bias (row-major) --------------------
__global__ void __launch_bounds__(256) sgemm_bias(
    const float* __restrict__ A, const float* __restrict__ B,
    const float* __restrict__ bias, float* __restrict__ C,
    int M, int Nn, int K)
{
    const int BM = 128, BN = 128, BK = 16;
    __shared__ float As[BK][BM];
    __shared__ float Bs[BK][BN];
    int tid = threadIdx.x;
    int bm = blockIdx.y * BM;
    int bn = blockIdx.x * BN;
    int tx = tid & 15, ty = tid >> 4;

    float acc[8][8];
#pragma unroll
    for (int i = 0; i < 8; i++)
#pragma unroll
        for (int j = 0; j < 8; j++) acc[i][j] = 0.f;

    int aRow = tid >> 2;          // 0..63
    int aCol = (tid & 3) * 4;     // 0,4,8,12
    int bRow = tid >> 5;          // 0..7
    int bCol = (tid & 31) * 4;    // 0..124

    for (int k0 = 0; k0 < K; k0 += BK) {
#pragma unroll
        for (int p = 0; p < 2; p++) {
            float4 v = *(const float4*)(A + (size_t)(bm + aRow + p * 64) * K + k0 + aCol);
            As[aCol + 0][aRow + p * 64] = v.x;
            As[aCol + 1][aRow + p * 64] = v.y;
            As[aCol + 2][aRow + p * 64] = v.z;
            As[aCol + 3][aRow + p * 64] = v.w;
        }
#pragma unroll
        for (int p = 0; p < 2; p++) {
            *(float4*)&Bs[bRow + p * 8][bCol] =
                *(const float4*)(B + (size_t)(k0 + bRow + p * 8) * Nn + bn + bCol);
        }
        __syncthreads();
#pragma unroll
        for (int kk = 0; kk < BK; kk++) {
            float a[8], b[8];
            *(float4*)&a[0] = *(const float4*)&As[kk][ty * 4];
            *(float4*)&a[4] = *(const float4*)&As[kk][64 + ty * 4];
            *(float4*)&b[0] = *(const float4*)&Bs[kk][tx * 4];
            *(float4*)&b[4] = *(const float4*)&Bs[kk][64 + tx * 4];
#pragma unroll
            for (int i = 0; i < 8; i++)
#pragma unroll
                for (int j = 0; j < 8; j++) acc[i][j] += a[i] * b[j];
        }
        __syncthreads();
    }
#pragma unroll
    for (int i = 0; i < 8; i++) {
        int r = bm + ((i < 4) ? (ty * 4 + i) : (64 + ty * 4 + i - 4));
#pragma unroll
        for (int half = 0; half < 2; half++) {
            int c = bn + (half == 0 ? tx * 4 : 64 + tx * 4);
            float4 o;
            o.x = acc[i][half * 4 + 0] + bias[c + 0];
            o.y = acc[i][half * 4 + 1] + bias[c + 1];
            o.z = acc[i][half * 4 + 2] + bias[c + 2];
            o.w = acc[i][half * 4 + 3] + bias[c + 3];
            *(float4*)(C + (size_t)r * Nn + c) = o;
        }
    }
}

// ---------------- elu + layernorm (+optional clip) ---------------------------
__global__ void __launch_bounds__(256) elu_ln(
    const float* __restrict__ in, const float* __restrict__ gamma,
    const float* __restrict__ beta, float* __restrict__ out, int doClip)
{
    __shared__ float red[8];
    __shared__ float s_mu, s_w;
    int n = blockIdx.x;
    int tid = threadIdx.x;
    const float* row = in + (size_t)n * FDIM;
    float y[3];
    float s = 0.f;
#pragma unroll
    for (int i = 0; i < 3; i++) {
        float v = row[tid + i * 256];
        y[i] = v > 0.f ? v : expm1f(v);
        s += y[i];
    }
    float tot = block_reduce_256(s, red);
    if (tid == 0) s_mu = tot * (1.f / FDIM);
    __syncthreads();
    float mu = s_mu;
    float q = 0.f;
#pragma unroll
    for (int i = 0; i < 3; i++) { float d = y[i] - mu; q += d * d; }
    float totq = block_reduce_256(q, red);
    if (tid == 0) s_w = rsqrtf(totq * (1.f / FDIM) + 1e-5f);
    __syncthreads();
    float w = s_w;
#pragma unroll
    for (int i = 0; i < 3; i++) {
        int d = tid + i * 256;
        float o = (y[i] - mu) * w * gamma[d] + beta[d];
        if (doClip) o = fminf(fmaxf(o, -10000.f), 10000.f);
        out[(size_t)n * FDIM + d] = o;
    }
}

// ---------------- launch ------------------------------------------------------
extern "C" void kernel_launch(void* const* d_in, const int* in_sizes, int n_in,
                              void* d_out, int out_size)
{
    const float* x   = (const float*)d_in[0];
    const void*  ei  = d_in[1];
    const float* W1  = (const float*)d_in[2];
    const float* a1s = (const float*)d_in[3];
    const float* a1d = (const float*)d_in[4];
    const float* b1  = (const float*)d_in[5];
    const float* W2  = (const float*)d_in[6];
    const float* a2s = (const float*)d_in[7];
    const float* a2d = (const float*)d_in[8];
    const float* b2  = (const float*)d_in[9];
    const float* gm  = (const float*)d_in[10];
    const float* bt  = (const float*)d_in[11];
    float* out = (float*)d_out;

    float *p1, *p2, *w1p, *e1, *e2, *agg1, *agg2, *pre, *x1;
    cudaGetSymbolAddress((void**)&p1,   g_P1);
    cudaGetSymbolAddress((void**)&p2,   g_P2);
    cudaGetSymbolAddress((void**)&w1p,  g_W1p);
    cudaGetSymbolAddress((void**)&e1,   g_e1);
    cudaGetSymbolAddress((void**)&e2,   g_e2);
    cudaGetSymbolAddress((void**)&agg1, g_agg1);
    cudaGetSymbolAddress((void**)&agg2, g_agg2);
    cudaGetSymbolAddress((void**)&pre,  g_pre);
    cudaGetSymbolAddress((void**)&x1,   g_x1);

    detect_kernel<<<1, 256>>>((const unsigned long long*)ei);
    build_p<<<dim3(FDIM, 10), 256>>>(W1, a1s, a1d, W2, a2s, a2d);
    build_w1p<<<(int)(((size_t)4 * FDIM * FDIM + 255) / 256), 256>>>(W1);

    // layer 1
    compute_e<8><<<512, 256>>>(x, p1, e1);
    aggregate<4, 8><<<NNODES, 256>>>(x, e1, ei, agg1);
    sgemm_bias<<<dim3(FDIM / 128, NNODES / 128), 256>>>(agg1, w1p, b1, pre,
                                                        NNODES, FDIM, 4 * FDIM);
    elu_ln<<<NNODES, 256>>>(pre, gm, bt, x1, 0);

    // layer 2
    compute_e<2><<<512, 256>>>(x1, p2, e2);
    aggregate<1, 2><<<NNODES, 256>>>(x1, e2, ei, agg2);
    sgemm_bias<<<dim3(FDIM / 128, NNODES / 128), 256>>>(agg2, W2, b2, pre,
                                                        NNODES, FDIM, FDIM);
    elu_ln<<<NNODES, 256>>>(pre, gm, bt, out, 1);
}

// round 3
// speedup vs baseline: 2.5071x; 2.5071x over previous
#include <cuda_runtime.h>
#include <cstdint>
#include <cstddef>

#define NNODES 16384
#define FDIM   768
#define DEG    4

// ---------------- scratch (device globals; no allocation allowed) ----------
__device__ float g_P1[FDIM * 8];
__device__ float g_P2[FDIM * 2];
__device__ float g_W1p[(size_t)4 * FDIM * FDIM];     // [3072,768] B for GEMM1 (x0.25, tf32-rounded)
__device__ float g_W2r[(size_t)FDIM * FDIM];         // [768,768]  B for GEMM2 (tf32-rounded)
__device__ float g_e1[(size_t)NNODES * 8];
__device__ float g_e2[(size_t)NNODES * 2];
__device__ float g_agg1[(size_t)NNODES * 4 * FDIM];  // [N,3072] A for GEMM1 (tf32-rounded)
__device__ float g_agg2[(size_t)NNODES * FDIM];      // [N,768]  A for GEMM2 (tf32-rounded)
__device__ float g_pre[(size_t)NNODES * FDIM];
__device__ float g_x1[(size_t)NNODES * FDIM];
__device__ int   g_is64;

// ---------------- helpers ---------------------------------------------------
__device__ __forceinline__ uint32_t smem_u32(const void* p) {
    uint32_t a;
    asm("{ .reg .u64 t; cvta.to.shared.u64 t, %1; cvt.u32.u64 %0, t; }" : "=r"(a) : "l"(p));
    return a;
}

__device__ __forceinline__ float tf32_rne(float x) {
    uint32_t r;
    asm("cvt.rna.tf32.f32 %0, %1;" : "=r"(r) : "f"(x));
    return __uint_as_float(r);
}

__device__ __forceinline__ void cp16(uint32_t s, const void* g) {
    asm volatile("cp.async.cg.shared.global [%0], [%1], 16;" :: "r"(s), "l"(g));
}

__device__ __forceinline__ void mma_tf32(float* d, const uint32_t* a, const uint32_t* b) {
    asm volatile(
        "mma.sync.aligned.m16n8k8.row.col.f32.tf32.tf32.f32 "
        "{%0,%1,%2,%3}, {%4,%5,%6,%7}, {%8,%9}, {%0,%1,%2,%3};"
        : "+f"(d[0]), "+f"(d[1]), "+f"(d[2]), "+f"(d[3])
        : "r"(a[0]), "r"(a[1]), "r"(a[2]), "r"(a[3]), "r"(b[0]), "r"(b[1]));
}

__device__ __forceinline__ float block_reduce_256(float v, float* red) {
#pragma unroll
    for (int o = 16; o; o >>= 1) v += __shfl_down_sync(0xffffffffu, v, o);
    if ((threadIdx.x & 31) == 0) red[threadIdx.x >> 5] = v;
    __syncthreads();
    float r = 0.f;
    if (threadIdx.x < 8) r = red[threadIdx.x];
    if (threadIdx.x < 32) {
#pragma unroll
        for (int o = 4; o; o >>= 1) r += __shfl_down_sync(0xffu, r, o);
    }
    return r;
}

// ---------------- edge dtype probe ------------------------------------------
__global__ void detect_kernel(const unsigned long long* __restrict__ p) {
    __shared__ int bad;
    if (threadIdx.x == 0) bad = 0;
    __syncthreads();
    for (int i = threadIdx.x; i < 1024; i += blockDim.x)
        if (p[i] > 0xFFFFFFFFull) bad = 1;
    __syncthreads();
    if (threadIdx.x == 0) g_is64 = bad ? 0 : 1;
}

// ---------------- attention projection vectors P = W_h @ a_h ----------------
__global__ void __launch_bounds__(256) build_p(
    const float* __restrict__ W1, const float* __restrict__ a1s, const float* __restrict__ a1d,
    const float* __restrict__ W2, const float* __restrict__ a2s, const float* __restrict__ a2d)
{
    __shared__ float red[8];
    int k = blockIdx.x, j = blockIdx.y;
    const float *w, *a;
    if (j < 8) {
        int h = j & 3;
        w = W1 + (size_t)k * (4 * FDIM) + h * FDIM;
        a = (j < 4 ? a1s : a1d) + h * FDIM;
    } else {
        w = W2 + (size_t)k * FDIM;
        a = (j == 8) ? a2s : a2d;
    }
    float s = 0.f;
    for (int d = threadIdx.x; d < FDIM; d += 256) s += w[d] * a[d];
    float tot = block_reduce_256(s, red);
    if (threadIdx.x == 0) {
        if (j < 8) g_P1[k * 8 + j] = tot;
        else       g_P2[k * 2 + (j - 8)] = tot;
    }
}

// ---------------- repack W1 (head-mean fold) + round W2 to tf32 -------------
__global__ void __launch_bounds__(256) build_w1p(const float* __restrict__ W1) {
    size_t idx = (size_t)blockIdx.x * 256 + threadIdx.x;
    if (idx >= (size_t)4 * FDIM * FDIM) return;
    int j = (int)(idx % FDIM);
    int r = (int)(idx / FDIM);     // h*768 + k
    int h = r / FDIM, k = r % FDIM;
    g_W1p[idx] = tf32_rne(0.25f * W1[(size_t)k * (4 * FDIM) + h * FDIM + j]);
}

__global__ void __launch_bounds__(256) build_w2r(const float* __restrict__ W2) {
    size_t idx = (size_t)blockIdx.x * 256 + threadIdx.x;
    if (idx < (size_t)FDIM * FDIM) g_W2r[idx] = tf32_rne(W2[idx]);
}

// ---------------- per-node logits e = x @ P ----------------------------------
template <int NJ>
__global__ void __launch_bounds__(256) compute_e(
    const float* __restrict__ x, const float* __restrict__ P, float* __restrict__ e)
{
    __shared__ float sP[FDIM * NJ];
    for (int i = threadIdx.x; i < FDIM * NJ; i += 256) sP[i] = P[i];
    __syncthreads();
    int warp = threadIdx.x >> 5, lane = threadIdx.x & 31;
    for (int n = blockIdx.x * 8 + warp; n < NNODES; n += gridDim.x * 8) {
        const float* xr = x + (size_t)n * FDIM;
        float acc[NJ];
#pragma unroll
        for (int j = 0; j < NJ; j++) acc[j] = 0.f;
        for (int k = lane; k < FDIM; k += 32) {
            float xv = xr[k];
#pragma unroll
            for (int j = 0; j < NJ; j++) acc[j] += xv * sP[k * NJ + j];
        }
#pragma unroll
        for (int j = 0; j < NJ; j++) {
            float v = acc[j];
#pragma unroll
            for (int o = 16; o; o >>= 1) v += __shfl_down_sync(0xffffffffu, v, o);
            if (lane == 0) e[(size_t)n * NJ + j] = v;
        }
    }
}

// ---------------- softmax + weighted gather in x-space ----------------------
template <int H, int NJ>
__global__ void __launch_bounds__(256) aggregate(
    const float* __restrict__ x, const float* __restrict__ e,
    const void* __restrict__ edge, float* __restrict__ agg)
{
    int n = blockIdx.x;
    __shared__ int   s_src[5];
    __shared__ float s_alpha[H][5];
    int tid = threadIdx.x;
    if (tid < 5) {
        int sv = n;
        if (tid < 4) {
            sv = g_is64 ? (int)((const long long*)edge)[(size_t)DEG * n + tid]
                        : ((const int*)edge)[DEG * n + tid];
        }
        s_src[tid] = sv;
    }
    __syncthreads();
    if (tid < H) {
        float ed = e[(size_t)n * NJ + H + tid];
        float l[5];
#pragma unroll
        for (int k = 0; k < 5; k++) {
            float v = e[(size_t)s_src[k] * NJ + tid] + ed;
            l[k] = v >= 0.f ? v : 0.2f * v;
        }
        float m = l[0];
#pragma unroll
        for (int k = 1; k < 5; k++) m = fmaxf(m, l[k]);
        float s = 0.f;
#pragma unroll
        for (int k = 0; k < 5; k++) { l[k] = expf(l[k] - m); s += l[k]; }
        float inv = 1.f / (s + 1e-16f);
#pragma unroll
        for (int k = 0; k < 5; k++) s_alpha[tid][k] = l[k] * inv;
    }
    __syncthreads();
    for (int d = tid; d < FDIM; d += 256) {
        float xv[5];
#pragma unroll
        for (int k = 0; k < 5; k++) xv[k] = x[(size_t)s_src[k] * FDIM + d];
#pragma unroll
        for (int h = 0; h < H; h++) {
            float a0 = 0.f;
#pragma unroll
            for (int k = 0; k < 5; k++) a0 += s_alpha[h][k] * xv[k];
            agg[((size_t)n * H + h) * FDIM + d] = tf32_rne(a0);
        }
    }
}

// ---------------- tf32 mma.sync GEMM: C = A[M,K] @ B[K,N] + bias ------------
// CTA tile 128x128, BK=32, 8 warps (2x4), warp tile 64x32, double-buffered cp.async.
#define BM 128
#define BN 128
#define BK 32
#define ASTR 36
#define BSTR 132
#define GEMM_SMEM (2 * (BM * ASTR + BK * BSTR) * 4)

__global__ void __launch_bounds__(256, 2) gemm_mma(
    const float* __restrict__ A, const float* __restrict__ B,
    const float* __restrict__ bias, float* __restrict__ C,
    int Nn, int K)
{
    extern __shared__ float dsm[];
    float* As = dsm;                          // [2][BM*ASTR]
    float* Bs = dsm + 2 * BM * ASTR;          // [2][BK*BSTR]
    uint32_t asb = smem_u32(As), bsb = smem_u32(Bs);

    int tid = threadIdx.x;
    int bm = blockIdx.y * BM, bn = blockIdx.x * BN;
    int lane = tid & 31, wid = tid >> 5;
    int warpM = wid & 1, warpN = wid >> 1;
    int g = lane >> 2, tg = lane & 3;

    float acc[4][4][4];
#pragma unroll
    for (int i = 0; i < 4; i++)
#pragma unroll
        for (int j = 0; j < 4; j++)
#pragma unroll
            for (int r = 0; r < 4; r++) acc[i][j][r] = 0.f;

    auto load_stage = [&](int s, int k0) {
#pragma unroll
        for (int t = 0; t < 4; t++) {
            int i = tid + t * 256;
            int r = i >> 3, c4 = i & 7;
            cp16(asb + (uint32_t)(s * BM * ASTR + r * ASTR + c4 * 4) * 4,
                 A + (size_t)(bm + r) * K + k0 + c4 * 4);
        }
#pragma unroll
        for (int t = 0; t < 4; t++) {
            int i = tid + t * 256;
            int r = i >> 5, c4 = i & 31;
            cp16(bsb + (uint32_t)(s * BK * BSTR + r * BSTR + c4 * 4) * 4,
                 B + (size_t)(k0 + r) * Nn + bn + c4 * 4);
        }
        asm volatile("cp.async.commit_group;");
    };

    int KT = K / BK;
    load_stage(0, 0);
    for (int kt = 0; kt < KT; kt++) {
        int buf = kt & 1;
        if (kt + 1 < KT) {
            load_stage(buf ^ 1, (kt + 1) * BK);
            asm volatile("cp.async.wait_group 1;");
        } else {
            asm volatile("cp.async.wait_group 0;");
        }
        __syncthreads();
        const float* a_s = As + buf * BM * ASTR;
        const float* b_s = Bs + buf * BK * BSTR;
#pragma unroll
        for (int ks = 0; ks < 4; ks++) {
            int kk = ks * 8;
            uint32_t af[4][4];
#pragma unroll
            for (int mt = 0; mt < 4; mt++) {
                int m = warpM * 64 + mt * 16 + g;
                af[mt][0] = __float_as_uint(a_s[m * ASTR + kk + tg]);
                af[mt][1] = __float_as_uint(a_s[(m + 8) * ASTR + kk + tg]);
                af[mt][2] = __float_as_uint(a_s[m * ASTR + kk + tg + 4]);
                af[mt][3] = __float_as_uint(a_s[(m + 8) * ASTR + kk + tg + 4]);
            }
            uint32_t bf[4][2];
#pragma unroll
            for (int nt = 0; nt < 4; nt++) {
                int n = warpN * 32 + nt * 8 + g;
                bf[nt][0] = __float_as_uint(b_s[(kk + tg) * BSTR + n]);
                bf[nt][1] = __float_as_uint(b_s[(kk + tg + 4) * BSTR + n]);
            }
#pragma unroll
            for (int mt = 0; mt < 4; mt++)
#pragma unroll
                for (int nt = 0; nt < 4; nt++)
                    mma_tf32(acc[mt][nt], af[mt], bf[nt]);
        }
        __syncthreads();
    }

    // epilogue: bias add + store
#pragma unroll
    for (int mt = 0; mt < 4; mt++) {
        int row = bm + warpM * 64 + mt * 16 + g;
#pragma unroll
        for (int nt = 0; nt < 4; nt++) {
            int col = bn + warpN * 32 + nt * 8 + tg * 2;
            float b0 = bias[col], b1 = bias[col + 1];
            float2 v0 = make_float2(acc[mt][nt][0] + b0, acc[mt][nt][1] + b1);
            float2 v1 = make_float2(acc[mt][nt][2] + b0, acc[mt][nt][3] + b1);
            *(float2*)(C + (size_t)row * Nn + col) = v0;
            *(float2*)(C + (size_t)(row + 8) * Nn + col) = v1;
        }
    }
}

// ---------------- elu + layernorm (+optional clip) ---------------------------
__global__ void __launch_bounds__(256) elu_ln(
    const float* __restrict__ in, const float* __restrict__ gamma,
    const float* __restrict__ beta, float* __restrict__ out, int doClip)
{
    __shared__ float red[8];
    __shared__ float s_mu, s_w;
    int n = blockIdx.x;
    int tid = threadIdx.x;
    const float* row = in + (size_t)n * FDIM;
    float y[3];
    float s = 0.f;
#pragma unroll
    for (int i = 0; i < 3; i++) {
        float v = row[tid + i * 256];
        y[i] = v > 0.f ? v : expm1f(v);
        s += y[i];
    }
    float tot = block_reduce_256(s, red);
    if (tid == 0) s_mu = tot * (1.f / FDIM);
    __syncthreads();
    float mu = s_mu;
    float q = 0.f;
#pragma unroll
    for (int i = 0; i < 3; i++) { float d = y[i] - mu; q += d * d; }
    float totq = block_reduce_256(q, red);
    if (tid == 0) s_w = rsqrtf(totq * (1.f / FDIM) + 1e-5f);
    __syncthreads();
    float w = s_w;
#pragma unroll
    for (int i = 0; i < 3; i++) {
        int d = tid + i * 256;
        float o = (y[i] - mu) * w * gamma[d] + beta[d];
        if (doClip) o = fminf(fmaxf(o, -10000.f), 10000.f);
        out[(size_t)n * FDIM + d] = o;
    }
}

// ---------------- launch ------------------------------------------------------
extern "C" void kernel_launch(void* const* d_in, const int* in_sizes, int n_in,
                              void* d_out, int out_size)
{
    const float* x   = (const float*)d_in[0];
    const void*  ei  = d_in[1];
    const float* W1  = (const float*)d_in[2];
    const float* a1s = (const float*)d_in[3];
    const float* a1d = (const float*)d_in[4];
    const float* b1  = (const float*)d_in[5];
    const float* W2  = (const float*)d_in[6];
    const float* a2s = (const float*)d_in[7];
    const float* a2d = (const float*)d_in[8];
    const float* b2  = (const float*)d_in[9];
    const float* gm  = (const float*)d_in[10];
    const float* bt  = (const float*)d_in[11];
    float* out = (float*)d_out;

    float *p1, *p2, *w1p, *w2r, *e1, *e2, *agg1, *agg2, *pre, *x1;
    cudaGetSymbolAddress((void**)&p1,   g_P1);
    cudaGetSymbolAddress((void**)&p2,   g_P2);
    cudaGetSymbolAddress((void**)&w1p,  g_W1p);
    cudaGetSymbolAddress((void**)&w2r,  g_W2r);
    cudaGetSymbolAddress((void**)&e1,   g_e1);
    cudaGetSymbolAddress((void**)&e2,   g_e2);
    cudaGetSymbolAddress((void**)&agg1, g_agg1);
    cudaGetSymbolAddress((void**)&agg2, g_agg2);
    cudaGetSymbolAddress((void**)&pre,  g_pre);
    cudaGetSymbolAddress((void**)&x1,   g_x1);

    cudaFuncSetAttribute(gemm_mma, cudaFuncAttributeMaxDynamicSharedMemorySize, GEMM_SMEM);

    detect_kernel<<<1, 256>>>((const unsigned long long*)ei);
    build_p<<<dim3(FDIM, 10), 256>>>(W1, a1s, a1d, W2, a2s, a2d);
    build_w1p<<<(int)(((size_t)4 * FDIM * FDIM + 255) / 256), 256>>>(W1);
    build_w2r<<<(int)(((size_t)FDIM * FDIM + 255) / 256), 256>>>(W2);

    // layer 1
    compute_e<8><<<512, 256>>>(x, p1, e1);
    aggregate<4, 8><<<NNODES, 256>>>(x, e1, ei, agg1);
    gemm_mma<<<dim3(FDIM / BN, NNODES / BM), 256, GEMM_SMEM>>>(agg1, w1p, b1, pre,
                                                               FDIM, 4 * FDIM);
    elu_ln<<<NNODES, 256>>>(pre, gm, bt, x1, 0);

    // layer 2
    compute_e<2><<<512, 256>>>(x1, p2, e2);
    aggregate<1, 2><<<NNODES, 256>>>(x1, e2, ei, agg2);
    gemm_mma<<<dim3(FDIM / BN, NNODES / BM), 256, GEMM_SMEM>>>(agg2, w2r, b2, pre,
                                                               FDIM, FDIM);
    elu_ln<<<NNODES, 256>>>(pre, gm, bt, out, 1);
}

// round 4
// speedup vs baseline: 4.1721x; 1.6641x over previous
#include <cuda_runtime.h>
#include <cuda_fp16.h>
#include <cstdint>
#include <cstddef>

#define NNODES 16384
#define FDIM   768
#define DEG    4

// ---------------- scratch (device globals; no allocation allowed) ----------
__device__ float  g_P1[FDIM * 8];
__device__ float  g_P2[FDIM * 2];
__device__ __half g_W1ph[(size_t)4 * FDIM * FDIM];    // [3072,768] B GEMM1 (x0.25, fp16)
__device__ __half g_W2rh[(size_t)FDIM * FDIM];        // [768,768]  B GEMM2 (fp16)
__device__ float  g_e1[(size_t)NNODES * 8];
__device__ float  g_e2[(size_t)NNODES * 2];
__device__ __half g_agg1h[(size_t)NNODES * 4 * FDIM]; // [N,3072] A GEMM1 (fp16)
__device__ __half g_agg2h[(size_t)NNODES * FDIM];     // [N,768]  A GEMM2 (fp16)
__device__ float  g_pre[(size_t)NNODES * FDIM];
__device__ float  g_x1[(size_t)NNODES * FDIM];
__device__ int    g_is64;

// ---------------- helpers ---------------------------------------------------
__device__ __forceinline__ uint32_t smem_u32(const void* p) {
    uint32_t a;
    asm("{ .reg .u64 t; cvta.to.shared.u64 t, %1; cvt.u32.u64 %0, t; }" : "=r"(a) : "l"(p));
    return a;
}

__device__ __forceinline__ void cp16(uint32_t s, const void* g) {
    asm volatile("cp.async.cg.shared.global [%0], [%1], 16;" :: "r"(s), "l"(g));
}

__device__ __forceinline__ void ldsm_x4(uint32_t* r, uint32_t addr) {
    asm volatile("ldmatrix.sync.aligned.m8n8.x4.shared.b16 {%0,%1,%2,%3}, [%4];"
                 : "=r"(r[0]), "=r"(r[1]), "=r"(r[2]), "=r"(r[3]) : "r"(addr));
}

__device__ __forceinline__ void ldsm_x4_t(uint32_t* r, uint32_t addr) {
    asm volatile("ldmatrix.sync.aligned.m8n8.x4.trans.shared.b16 {%0,%1,%2,%3}, [%4];"
                 : "=r"(r[0]), "=r"(r[1]), "=r"(r[2]), "=r"(r[3]) : "r"(addr));
}

__device__ __forceinline__ void mma_f16(float* d, const uint32_t* a, const uint32_t* b) {
    asm volatile(
        "mma.sync.aligned.m16n8k16.row.col.f32.f16.f16.f32 "
        "{%0,%1,%2,%3}, {%4,%5,%6,%7}, {%8,%9}, {%0,%1,%2,%3};"
        : "+f"(d[0]), "+f"(d[1]), "+f"(d[2]), "+f"(d[3])
        : "r"(a[0]), "r"(a[1]), "r"(a[2]), "r"(a[3]), "r"(b[0]), "r"(b[1]));
}

__device__ __forceinline__ float block_reduce_256(float v, float* red) {
#pragma unroll
    for (int o = 16; o; o >>= 1) v += __shfl_down_sync(0xffffffffu, v, o);
    if ((threadIdx.x & 31) == 0) red[threadIdx.x >> 5] = v;
    __syncthreads();
    float r = 0.f;
    if (threadIdx.x < 8) r = red[threadIdx.x];
    if (threadIdx.x < 32) {
#pragma unroll
        for (int o = 4; o; o >>= 1) r += __shfl_down_sync(0xffu, r, o);
    }
    return r;
}

// ---------------- edge dtype probe ------------------------------------------
__global__ void detect_kernel(const unsigned long long* __restrict__ p) {
    __shared__ int bad;
    if (threadIdx.x == 0) bad = 0;
    __syncthreads();
    for (int i = threadIdx.x; i < 1024; i += blockDim.x)
        if (p[i] > 0xFFFFFFFFull) bad = 1;
    __syncthreads();
    if (threadIdx.x == 0) g_is64 = bad ? 0 : 1;
}

// ---------------- attention projection vectors P = W_h @ a_h ----------------
__global__ void __launch_bounds__(256) build_p(
    const float* __restrict__ W1, const float* __restrict__ a1s, const float* __restrict__ a1d,
    const float* __restrict__ W2, const float* __restrict__ a2s, const float* __restrict__ a2d)
{
    __shared__ float red[8];
    int k = blockIdx.x, j = blockIdx.y;
    const float *w, *a;
    if (j < 8) {
        int h = j & 3;
        w = W1 + (size_t)k * (4 * FDIM) + h * FDIM;
        a = (j < 4 ? a1s : a1d) + h * FDIM;
    } else {
        w = W2 + (size_t)k * FDIM;
        a = (j == 8) ? a2s : a2d;
    }
    float s = 0.f;
    for (int d = threadIdx.x; d < FDIM; d += 256) s += w[d] * a[d];
    float tot = block_reduce_256(s, red);
    if (threadIdx.x == 0) {
        if (j < 8) g_P1[k * 8 + j] = tot;
        else       g_P2[k * 2 + (j - 8)] = tot;
    }
}

// ---------------- repack W1 (head-mean fold) + W2 to fp16 -------------------
__global__ void __launch_bounds__(256) build_w1p(const float* __restrict__ W1) {
    size_t idx = (size_t)blockIdx.x * 256 + threadIdx.x;
    if (idx >= (size_t)4 * FDIM * FDIM) return;
    int j = (int)(idx % FDIM);
    int r = (int)(idx / FDIM);     // h*768 + k
    int h = r / FDIM, k = r % FDIM;
    g_W1ph[idx] = __float2half(0.25f * W1[(size_t)k * (4 * FDIM) + h * FDIM + j]);
}

__global__ void __launch_bounds__(256) build_w2r(const float* __restrict__ W2) {
    size_t idx = (size_t)blockIdx.x * 256 + threadIdx.x;
    if (idx < (size_t)FDIM * FDIM) g_W2rh[idx] = __float2half(W2[idx]);
}

// ---------------- per-node logits e = x @ P ----------------------------------
template <int NJ>
__global__ void __launch_bounds__(256) compute_e(
    const float* __restrict__ x, const float* __restrict__ P, float* __restrict__ e)
{
    __shared__ float sP[FDIM * NJ];
    for (int i = threadIdx.x; i < FDIM * NJ; i += 256) sP[i] = P[i];
    __syncthreads();
    int warp = threadIdx.x >> 5, lane = threadIdx.x & 31;
    for (int n = blockIdx.x * 8 + warp; n < NNODES; n += gridDim.x * 8) {
        const float* xr = x + (size_t)n * FDIM;
        float acc[NJ];
#pragma unroll
        for (int j = 0; j < NJ; j++) acc[j] = 0.f;
        for (int k = lane; k < FDIM; k += 32) {
            float xv = xr[k];
#pragma unroll
            for (int j = 0; j < NJ; j++) acc[j] += xv * sP[k * NJ + j];
        }
#pragma unroll
        for (int j = 0; j < NJ; j++) {
            float v = acc[j];
#pragma unroll
            for (int o = 16; o; o >>= 1) v += __shfl_down_sync(0xffffffffu, v, o);
            if (lane == 0) e[(size_t)n * NJ + j] = v;
        }
    }
}

// ---------------- softmax + weighted gather in x-space (fp16 out) -----------
template <int H, int NJ>
__global__ void __launch_bounds__(256) aggregate(
    const float* __restrict__ x, const float* __restrict__ e,
    const void* __restrict__ edge, __half* __restrict__ agg)
{
    int n = blockIdx.x;
    __shared__ int   s_src[5];
    __shared__ float s_alpha[H][5];
    int tid = threadIdx.x;
    if (tid < 5) {
        int sv = n;
        if (tid < 4) {
            sv = g_is64 ? (int)((const long long*)edge)[(size_t)DEG * n + tid]
                        : ((const int*)edge)[DEG * n + tid];
        }
        s_src[tid] = sv;
    }
    __syncthreads();
    if (tid < H) {
        float ed = e[(size_t)n * NJ + H + tid];
        float l[5];
#pragma unroll
        for (int k = 0; k < 5; k++) {
            float v = e[(size_t)s_src[k] * NJ + tid] + ed;
            l[k] = v >= 0.f ? v : 0.2f * v;
        }
        float m = l[0];
#pragma unroll
        for (int k = 1; k < 5; k++) m = fmaxf(m, l[k]);
        float s = 0.f;
#pragma unroll
        for (int k = 0; k < 5; k++) { l[k] = expf(l[k] - m); s += l[k]; }
        float inv = 1.f / (s + 1e-16f);
#pragma unroll
        for (int k = 0; k < 5; k++) s_alpha[tid][k] = l[k] * inv;
    }
    __syncthreads();
    for (int d = tid; d < FDIM; d += 256) {
        float xv[5];
#pragma unroll
        for (int k = 0; k < 5; k++) xv[k] = x[(size_t)s_src[k] * FDIM + d];
#pragma unroll
        for (int h = 0; h < H; h++) {
            float a0 = 0.f;
#pragma unroll
            for (int k = 0; k < 5; k++) a0 += s_alpha[h][k] * xv[k];
            agg[((size_t)n * H + h) * FDIM + d] = __float2half(a0);
        }
    }
}

// ---------------- fp16 mma.sync GEMM: C = A[M,K] @ B[K,N] + bias ------------
// CTA 128x128, BK=32, 8 warps (2x4), warp tile 64x32, ldmatrix, 4-stage cp.async.
#define BM 128
#define BN 128
#define BK 32
#define ASTRH 40
#define BSTRH 136
#define A_STG (BM * ASTRH)
#define B_STG (BK * BSTRH)
#define NSTAGE 4
#define GEMM_SMEM (NSTAGE * (A_STG + B_STG) * 2)

__global__ void __launch_bounds__(256, 2) gemm_fp16(
    const __half* __restrict__ A, const __half* __restrict__ B,
    const float* __restrict__ bias, float* __restrict__ C,
    int Nn, int K)
{
    extern __shared__ __half hsm[];
    uint32_t asb = smem_u32(hsm);
    uint32_t bsb = asb + NSTAGE * A_STG * 2;

    int tid = threadIdx.x;
    int bm = blockIdx.y * BM, bn = blockIdx.x * BN;
    int lane = tid & 31, wid = tid >> 5;
    int warpM = wid & 1, warpN = wid >> 1;
    int g = lane >> 2, tg = lane & 3;

    float acc[4][4][4];
#pragma unroll
    for (int i = 0; i < 4; i++)
#pragma unroll
        for (int j = 0; j < 4; j++)
#pragma unroll
            for (int r = 0; r < 4; r++) acc[i][j][r] = 0.f;

    auto load_stage = [&](int s, int k0) {
#pragma unroll
        for (int t = 0; t < 2; t++) {
            int i = tid + t * 256;
            int r = i >> 2, c8 = (i & 3) * 8;
            cp16(asb + (uint32_t)(s * A_STG + r * ASTRH + c8) * 2,
                 A + (size_t)(bm + r) * K + k0 + c8);
        }
#pragma unroll
        for (int t = 0; t < 2; t++) {
            int i = tid + t * 256;
            int r = i >> 4, c8 = (i & 15) * 8;
            cp16(bsb + (uint32_t)(s * B_STG + r * BSTRH + c8) * 2,
                 B + (size_t)(k0 + r) * Nn + bn + c8);
        }
        asm volatile("cp.async.commit_group;");
    };

    // per-warp fragment base offsets (halves)
    uint32_t a_off = (uint32_t)((warpM * 64 + (lane & 15)) * ASTRH + (lane >> 4) * 8);
    uint32_t b_off = (uint32_t)((lane & 15) * BSTRH + warpN * 32 + (lane >> 4) * 8);

    int KT = K / BK;
    load_stage(0, 0);
    load_stage(1, BK);
    load_stage(2, 2 * BK);

    for (int kt = 0; kt < KT; kt++) {
        int pf = kt + 3;
        int pfk = (pf < KT ? pf : pf - KT) * BK;   // wrap: harmless dummy loads at tail
        load_stage(pf & 3, pfk);
        asm volatile("cp.async.wait_group 3;");
        __syncthreads();

        int buf = kt & 3;
        uint32_t a_base = asb + (buf * A_STG + a_off) * 2;
        uint32_t b_base = bsb + (buf * B_STG + b_off) * 2;
#pragma unroll
        for (int ks = 0; ks < 2; ks++) {
            uint32_t af[4][4], bf[2][4];
#pragma unroll
            for (int mt = 0; mt < 4; mt++)
                ldsm_x4(af[mt], a_base + (uint32_t)(mt * 16 * ASTRH + ks * 16) * 2);
#pragma unroll
            for (int np = 0; np < 2; np++)
                ldsm_x4_t(bf[np], b_base + (uint32_t)(ks * 16 * BSTRH + np * 16) * 2);
#pragma unroll
            for (int mt = 0; mt < 4; mt++)
#pragma unroll
                for (int np = 0; np < 2; np++) {
                    mma_f16(acc[mt][np * 2 + 0], af[mt], &bf[np][0]);
                    mma_f16(acc[mt][np * 2 + 1], af[mt], &bf[np][2]);
                }
        }
        __syncthreads();
    }

    // epilogue: bias add + store
#pragma unroll
    for (int mt = 0; mt < 4; mt++) {
        int row = bm + warpM * 64 + mt * 16 + g;
#pragma unroll
        for (int nt = 0; nt < 4; nt++) {
            int col = bn + warpN * 32 + nt * 8 + tg * 2;
            float b0 = bias[col], b1 = bias[col + 1];
            float2 v0 = make_float2(acc[mt][nt][0] + b0, acc[mt][nt][1] + b1);
            float2 v1 = make_float2(acc[mt][nt][2] + b0, acc[mt][nt][3] + b1);
            *(float2*)(C + (size_t)row * Nn + col) = v0;
            *(float2*)(C + (size_t)(row + 8) * Nn + col) = v1;
        }
    }
}

// ---------------- elu + layernorm (+optional clip) ---------------------------
__global__ void __launch_bounds__(256) elu_ln(
    const float* __restrict__ in, const float* __restrict__ gamma,
    const float* __restrict__ beta, float* __restrict__ out, int doClip)
{
    __shared__ float red[8];
    __shared__ float s_mu, s_w;
    int n = blockIdx.x;
    int tid = threadIdx.x;
    const float* row = in + (size_t)n * FDIM;
    float y[3];
    float s = 0.f;
#pragma unroll
    for (int i = 0; i < 3; i++) {
        float v = row[tid + i * 256];
        y[i] = v > 0.f ? v : expm1f(v);
        s += y[i];
    }
    float tot = block_reduce_256(s, red);
    if (tid == 0) s_mu = tot * (1.f / FDIM);
    __syncthreads();
    float mu = s_mu;
    float q = 0.f;
#pragma unroll
    for (int i = 0; i < 3; i++) { float d = y[i] - mu; q += d * d; }
    float totq = block_reduce_256(q, red);
    if (tid == 0) s_w = rsqrtf(totq * (1.f / FDIM) + 1e-5f);
    __syncthreads();
    float w = s_w;
#pragma unroll
    for (int i = 0; i < 3; i++) {
        int d = tid + i * 256;
        float o = (y[i] - mu) * w * gamma[d] + beta[d];
        if (doClip) o = fminf(fmaxf(o, -10000.f), 10000.f);
        out[(size_t)n * FDIM + d] = o;
    }
}

// ---------------- launch ------------------------------------------------------
extern "C" void kernel_launch(void* const* d_in, const int* in_sizes, int n_in,
                              void* d_out, int out_size)
{
    const float* x   = (const float*)d_in[0];
    const void*  ei  = d_in[1];
    const float* W1  = (const float*)d_in[2];
    const float* a1s = (const float*)d_in[3];
    const float* a1d = (const float*)d_in[4];
    const float* b1  = (const float*)d_in[5];
    const float* W2  = (const float*)d_in[6];
    const float* a2s = (const float*)d_in[7];
    const float* a2d = (const float*)d_in[8];
    const float* b2  = (const float*)d_in[9];
    const float* gm  = (const float*)d_in[10];
    const float* bt  = (const float*)d_in[11];
    float* out = (float*)d_out;

    float *p1, *p2, *e1, *e2, *pre, *x1;
    __half *w1ph, *w2rh, *agg1h, *agg2h;
    cudaGetSymbolAddress((void**)&p1,    g_P1);
    cudaGetSymbolAddress((void**)&p2,    g_P2);
    cudaGetSymbolAddress((void**)&w1ph,  g_W1ph);
    cudaGetSymbolAddress((void**)&w2rh,  g_W2rh);
    cudaGetSymbolAddress((void**)&e1,    g_e1);
    cudaGetSymbolAddress((void**)&e2,    g_e2);
    cudaGetSymbolAddress((void**)&agg1h, g_agg1h);
    cudaGetSymbolAddress((void**)&agg2h, g_agg2h);
    cudaGetSymbolAddress((void**)&pre,   g_pre);
    cudaGetSymbolAddress((void**)&x1,    g_x1);

    cudaFuncSetAttribute(gemm_fp16, cudaFuncAttributeMaxDynamicSharedMemorySize, GEMM_SMEM);

    detect_kernel<<<1, 256>>>((const unsigned long long*)ei);
    build_p<<<dim3(FDIM, 10), 256>>>(W1, a1s, a1d, W2, a2s, a2d);
    build_w1p<<<(int)(((size_t)4 * FDIM * FDIM + 255) / 256), 256>>>(W1);
    build_w2r<<<(int)(((size_t)FDIM * FDIM + 255) / 256), 256>>>(W2);

    // layer 1
    compute_e<8><<<512, 256>>>(x, p1, e1);
    aggregate<4, 8><<<NNODES, 256>>>(x, e1, ei, agg1h);
    gemm_fp16<<<dim3(FDIM / BN, NNODES / BM), 256, GEMM_SMEM>>>(agg1h, w1ph, b1, pre,
                                                                FDIM, 4 * FDIM);
    elu_ln<<<NNODES, 256>>>(pre, gm, bt, x1, 0);

    // layer 2
    compute_e<2><<<512, 256>>>(x1, p2, e2);
    aggregate<1, 2><<<NNODES, 256>>>(x1, e2, ei, agg2h);
    gemm_fp16<<<dim3(FDIM / BN, NNODES / BM), 256, GEMM_SMEM>>>(agg2h, w2rh, b2, pre,
                                                                FDIM, FDIM);
    elu_ln<<<NNODES, 256>>>(pre, gm, bt, out, 1);
}